// round 2
// baseline (speedup 1.0000x reference)
#include <cuda_runtime.h>
#include <cstdint>

#define Hh 512
#define Ww 512
#define Cc 32
#define Bb 4
#define Ss (Hh*Ww)

// Scratch: per-pixel (off_x, off_y), 4*512*512*8B = 8 MB
__device__ float2 g_off_buf[Bb * Ss];

typedef unsigned long long ull;

__device__ __forceinline__ ull pack2(float a, float b) {
    ull r;
    asm("mov.b64 %0, {%1, %2};" : "=l"(r) : "f"(a), "f"(b));
    return r;
}
__device__ __forceinline__ void unpack2(ull v, float& a, float& b) {
    asm("mov.b64 {%0, %1}, %2;" : "=f"(a), "=f"(b) : "l"(v));
}
__device__ __forceinline__ ull fma2(ull a, ull b, ull c) {
    ull d;
    asm("fma.rn.f32x2 %0, %1, %2, %3;" : "=l"(d) : "l"(a), "l"(b), "l"(c));
    return d;
}

// ---------------------------------------------------------------------------
// Kernel 1: offset conv. Only output channels 0,1 of the 18-channel conv are
// consumed by the reference (g[:, :, :, 0, :]), so compute exactly those.
// Tile 32x32 pixels per block, 128 threads, each thread = 4 cols x 2 rows.
// Channel loop with double-buffered smem staging (1 __syncthreads per channel).
// Accumulate (off_x, off_y) as a packed f32x2.
// ---------------------------------------------------------------------------
__global__ __launch_bounds__(128) void conv_off_kernel(
    const float* __restrict__ x,
    const float* __restrict__ w_off,
    const float* __restrict__ b_off)
{
    const int tid = threadIdx.x;
    const int cg = tid & 7;    // col group: cols 4cg..4cg+3
    const int rg = tid >> 3;   // row group: rows 2rg, 2rg+1
    const int bx = blockIdx.x, by = blockIdx.y, bz = blockIdx.z;

    __shared__ float2 s_w[Cc * 9];        // packed (w0, w1) per (c, k)
    __shared__ float  s_tile[2][34 * 36]; // (32+2) rows x (32+2) cols, padded to 36

    // Load the 2x32x9 weights once, packed as float2
    for (int i = tid; i < Cc * 9; i += 128)
        s_w[i] = make_float2(w_off[i], w_off[288 + i]);

    const int gx0 = bx * 32 - 1;
    const int gy0 = by * 32 - 1;
    const float* xb = x + (size_t)bz * Cc * Ss;

    auto stage = [&](int c, float* buf) {
        const float* xc = xb + (size_t)c * Ss;
        for (int i = tid; i < 34 * 34; i += 128) {
            int r = i / 34;
            int q = i - r * 34;
            int gy = gy0 + r;
            int gx = gx0 + q;
            float v = 0.0f;
            if ((unsigned)gy < (unsigned)Hh && (unsigned)gx < (unsigned)Ww)
                v = __ldg(xc + gy * Ww + gx);
            buf[r * 36 + q] = v;
        }
    };

    stage(0, s_tile[0]);
    const float b0v = __ldg(b_off + 0);
    const float b1v = __ldg(b_off + 1);
    __syncthreads();

    ull acc[8];
    const ull biasp = pack2(b0v, b1v);
#pragma unroll
    for (int i = 0; i < 8; i++) acc[i] = biasp;

    for (int c = 0; c < Cc; c++) {
        const float* curp = s_tile[c & 1];

        // per-channel packed weights (broadcast smem reads)
        ull wk[9];
#pragma unroll
        for (int k = 0; k < 9; k++) {
            float2 t = s_w[c * 9 + k];
            wk[k] = pack2(t.x, t.y);
        }

        // load 4 rows x 6 cols of input values for this thread's 4x2 pixels
        ull pv[4][6];
#pragma unroll
        for (int r = 0; r < 4; r++) {
            const float* rowp = curp + (2 * rg + r) * 36 + 4 * cg;
            float v0 = rowp[0], v1 = rowp[1], v2 = rowp[2];
            float v3 = rowp[3], v4 = rowp[4], v5 = rowp[5];
            pv[r][0] = pack2(v0, v0);
            pv[r][1] = pack2(v1, v1);
            pv[r][2] = pack2(v2, v2);
            pv[r][3] = pack2(v3, v3);
            pv[r][4] = pack2(v4, v4);
            pv[r][5] = pack2(v5, v5);
        }

        // prefetch next channel's tile into the other buffer
        if (c + 1 < Cc) stage(c + 1, s_tile[(c + 1) & 1]);

        // 9 taps x 8 pixels, packed (off_x, off_y)
#pragma unroll
        for (int pr = 0; pr < 2; pr++) {
#pragma unroll
            for (int pc = 0; pc < 4; pc++) {
                ull a = acc[pr * 4 + pc];
#pragma unroll
                for (int ky = 0; ky < 3; ky++) {
#pragma unroll
                    for (int kx = 0; kx < 3; kx++) {
                        a = fma2(pv[pr + ky][pc + kx], wk[ky * 3 + kx], a);
                    }
                }
                acc[pr * 4 + pc] = a;
            }
        }
        __syncthreads();
    }

    // write offsets
#pragma unroll
    for (int pr = 0; pr < 2; pr++) {
#pragma unroll
        for (int pc = 0; pc < 4; pc++) {
            int y = by * 32 + 2 * rg + pr;
            int xcol = bx * 32 + 4 * cg + pc;
            float ox, oy;
            unpack2(acc[pr * 4 + pc], ox, oy);
            g_off_buf[bz * Ss + y * Ww + xcol] = make_float2(ox, oy);
        }
    }
}

// ---------------------------------------------------------------------------
// Kernel 2: bilinear sampling, zero padding. One thread per output pixel,
// looping the 32 channels with corner indices/weights hoisted. The normalize/
// denormalize in the reference cancels: ix = x + off_x, iy = y + off_y.
//
// FIX vs previous round: clamp x0 and x1=x0+1 (and y) INDEPENDENTLY from the
// raw integer coordinate. Previously xi1 = min(511, clamp(xi0)+1) sampled
// column 1 instead of column 0 when x0 == -1 (ix in [-1,0)), which has a
// NONZERO weight in the reference -> 5e-2 rel_err at the edges.
// ---------------------------------------------------------------------------
__global__ __launch_bounds__(256) void sample_kernel(
    const float* __restrict__ x,
    float* __restrict__ out)
{
    const int px = blockIdx.x * 64 + threadIdx.x;
    const int py = blockIdx.y * 4 + threadIdx.y;
    const int b  = blockIdx.z;

    float2 off = g_off_buf[b * Ss + py * Ww + px];
    float ix = (float)px + off.x;
    float iy = (float)py + off.y;

    float x0f = floorf(ix);
    float y0f = floorf(iy);
    float wx1 = ix - x0f, wx0 = 1.0f - wx1;
    float wy1 = iy - y0f, wy0 = 1.0f - wy1;

    // validity of the four corners (x1 = x0+1, y1 = y0+1)
    float fx0 = (x0f >= 0.0f && x0f <= 511.0f) ? 1.0f : 0.0f;
    float fx1 = (x0f >= -1.0f && x0f <= 510.0f) ? 1.0f : 0.0f;
    float fy0 = (y0f >= 0.0f && y0f <= 511.0f) ? 1.0f : 0.0f;
    float fy1 = (y0f >= -1.0f && y0f <= 510.0f) ? 1.0f : 0.0f;

    // raw integer corners, clamped INDEPENDENTLY (matches jnp.clip semantics)
    int ix0r = (int)x0f;   // offsets are small; no fp->int range issues
    int iy0r = (int)y0f;
    int xi0 = max(0, min(511, ix0r));
    int xi1 = max(0, min(511, ix0r + 1));
    int yi0 = max(0, min(511, iy0r));
    int yi1 = max(0, min(511, iy0r + 1));

    float w00 = wy0 * wx0 * (fy0 * fx0);
    float w01 = wy0 * wx1 * (fy0 * fx1);
    float w10 = wy1 * wx0 * (fy1 * fx0);
    float w11 = wy1 * wx1 * (fy1 * fx1);

    const int i00 = yi0 * Ww + xi0;
    const int i01 = yi0 * Ww + xi1;
    const int i10 = yi1 * Ww + xi0;
    const int i11 = yi1 * Ww + xi1;

    const float* xb = x + (size_t)b * Cc * Ss;
    size_t o = (size_t)b * Cc * Ss + (size_t)py * Ww + px;

#pragma unroll 4
    for (int c = 0; c < Cc; c++) {
        const float* p = xb + (size_t)c * Ss;
        float v = w00 * __ldg(p + i00)
                + w01 * __ldg(p + i01)
                + w10 * __ldg(p + i10)
                + w11 * __ldg(p + i11);
        out[o + (size_t)c * Ss] = v;
    }
}

extern "C" void kernel_launch(void* const* d_in, const int* in_sizes, int n_in,
                              void* d_out, int out_size)
{
    const float* x     = (const float*)d_in[0];  // (4, 32, 512, 512)
    const float* w_off = (const float*)d_in[1];  // (18, 32, 3, 3)
    const float* b_off = (const float*)d_in[2];  // (18,)
    float* out = (float*)d_out;                  // (4, 32, 512, 512)

    (void)in_sizes; (void)n_in; (void)out_size;

    dim3 g1(Ww / 32, Hh / 32, Bb);
    conv_off_kernel<<<g1, 128>>>(x, w_off, b_off);

    dim3 g2(Ww / 64, Hh / 4, Bb);
    dim3 t2(64, 4);
    sample_kernel<<<g2, t2>>>(x, out);
}